// round 14
// baseline (speedup 1.0000x reference)
#include <cuda_runtime.h>
#include <cstdint>
#include <math.h>

#define B_  2
#define SQ_ 2048
#define SK_ 2048
#define D_  1024
#define H_  16
#define HD_ 64
#define SCALE_Q 0.180336880f   // 0.125 * log2(e); softmax via exp2

// ---------------------------------------------------------------------------
// Scratch (device globals — no allocation allowed)
// ---------------------------------------------------------------------------
__device__ float g_q[(size_t)B_ * H_ * SQ_ * HD_];     // rounded, pre-scaled by SCALE_Q
__device__ float g_k[(size_t)B_ * H_ * SK_ * HD_];     // rounded
__device__ float g_v[(size_t)B_ * H_ * HD_ * SK_];     // rounded, TRANSPOSED [hd][sk]
__device__ float g_attn[(size_t)B_ * SQ_ * D_];        // rounded
__device__ float g_xr[(size_t)B_ * SQ_ * D_];          // rounded x
__device__ float g_encr[(size_t)B_ * SK_ * D_];        // rounded enc
__device__ float g_wqt[(size_t)H_ * HD_ * D_];         // rounded, transposed: [h*HD+e][D]
__device__ float g_wkt[(size_t)H_ * HD_ * D_];
__device__ float g_wvt[(size_t)H_ * HD_ * D_];
__device__ float g_wot[(size_t)D_ * D_];               // rounded, transposed [n][k]

// ---------------------------------------------------------------------------
// helpers
// ---------------------------------------------------------------------------
__device__ __forceinline__ unsigned f2tf(float x) {
    unsigned u;
    asm("cvt.rna.tf32.f32 %0, %1;" : "=r"(u) : "f"(x));
    return u;
}
__device__ __forceinline__ float rndtf(float x) { return __uint_as_float(f2tf(x)); }

__device__ __forceinline__ void mma_tf32(float c[4],
    unsigned a0, unsigned a1, unsigned a2, unsigned a3,
    unsigned b0, unsigned b1)
{
    asm volatile(
        "mma.sync.aligned.m16n8k8.row.col.f32.tf32.tf32.f32 "
        "{%0,%1,%2,%3}, {%4,%5,%6,%7}, {%8,%9}, {%0,%1,%2,%3};\n"
        : "+f"(c[0]), "+f"(c[1]), "+f"(c[2]), "+f"(c[3])
        : "r"(a0), "r"(a1), "r"(a2), "r"(a3), "r"(b0), "r"(b1));
}

__device__ __forceinline__ void ldsm4(unsigned& r0, unsigned& r1,
                                      unsigned& r2, unsigned& r3, unsigned addr)
{
    asm volatile("ldmatrix.sync.aligned.m8n8.x4.shared.b16 {%0,%1,%2,%3}, [%4];"
        : "=r"(r0), "=r"(r1), "=r"(r2), "=r"(r3) : "r"(addr));
}

__device__ __forceinline__ void cpa16(unsigned dst, const void* src) {
    asm volatile("cp.async.cg.shared.global [%0], [%1], 16;" :: "r"(dst), "l"(src));
}
__device__ __forceinline__ void cpa_commit() {
    asm volatile("cp.async.commit_group;");
}
template <int N>
__device__ __forceinline__ void cpa_wait() {
    asm volatile("cp.async.wait_group %0;" :: "n"(N));
}

// ---------------------------------------------------------------------------
// Prep: round x and enc in one launch (blockIdx.y selects)
// ---------------------------------------------------------------------------
__global__ __launch_bounds__(256) void round2_kernel(
    const float* __restrict__ s0, const float* __restrict__ s1,
    float* __restrict__ d0, float* __restrict__ d1, int n4)
{
    int i = blockIdx.x * 256 + threadIdx.x;
    const float* s = blockIdx.y ? s1 : s0;
    float* d = blockIdx.y ? d1 : d0;
    if (i < n4) {
        float4 v = ((const float4*)s)[i];
        v.x = rndtf(v.x); v.y = rndtf(v.y);
        v.z = rndtf(v.z); v.w = rndtf(v.w);
        ((float4*)d)[i] = v;
    }
}

// ---------------------------------------------------------------------------
// Prep: transpose + round for the three QKV weights in one launch.
// ---------------------------------------------------------------------------
__global__ __launch_bounds__(256) void tround3_kernel(
    const float* __restrict__ s0, const float* __restrict__ s1,
    const float* __restrict__ s2,
    float* __restrict__ d0, float* __restrict__ d1, float* __restrict__ d2,
    int R, int C)
{
    __shared__ float tile[32][33];
    int zz = blockIdx.z;
    int which = zz >> 4;
    int z = zz & 15;
    const float* src = (which == 0) ? s0 : (which == 1) ? s1 : s2;
    float* dst = (which == 0) ? d0 : (which == 1) ? d1 : d2;
    src += (size_t)z * R * C;
    dst += (size_t)z * R * C;
    int c0 = blockIdx.x * 32, r0 = blockIdx.y * 32;
    int tx = threadIdx.x & 31, ty = threadIdx.x >> 5;

    #pragma unroll
    for (int i = ty; i < 32; i += 8)
        tile[i][tx] = src[(size_t)(r0 + i) * C + c0 + tx];
    __syncthreads();
    #pragma unroll
    for (int i = ty; i < 32; i += 8)
        dst[(size_t)(c0 + i) * R + r0 + tx] = rndtf(tile[tx][i]);
}

// ---------------------------------------------------------------------------
// Prep: transpose + round (single matrix, for Wo)
// ---------------------------------------------------------------------------
__global__ __launch_bounds__(256) void tround_kernel(
    const float* __restrict__ src, float* __restrict__ dst, int R, int C)
{
    __shared__ float tile[32][33];
    int c0 = blockIdx.x * 32, r0 = blockIdx.y * 32;
    int tx = threadIdx.x & 31, ty = threadIdx.x >> 5;

    #pragma unroll
    for (int i = ty; i < 32; i += 8)
        tile[i][tx] = src[(size_t)(r0 + i) * C + c0 + tx];
    __syncthreads();
    #pragma unroll
    for (int i = ty; i < 32; i += 8)
        dst[(size_t)(c0 + i) * R + r0 + tx] = rndtf(tile[tx][i]);
}

// ---------------------------------------------------------------------------
// Fused projection GEMM (1xTF32, LDSM fragments, 2-stage cp.async).
// MODE 0: Q gemm (N=1024); MODE 1: KV gemm (N=2048). (unchanged from R12)
// ---------------------------------------------------------------------------
template <int MODE>
__global__ __launch_bounds__(256) void gemm_big(
    const float* __restrict__ A, const float* __restrict__ BtK,
    const float* __restrict__ BtV, const float* __restrict__ biasK,
    const float* __restrict__ biasV, float* __restrict__ OutK,
    float* __restrict__ OutV)
{
    extern __shared__ float sm[];
    const unsigned smb = (unsigned)__cvta_generic_to_shared(sm);

    const int m0  = blockIdx.x * 128;
    const int n0g = blockIdx.y * 128;
    const bool isV = (MODE == 1) && (n0g >= 1024);
    const float* Bt = isV ? BtV + (size_t)(n0g - 1024) * D_
                          : BtK + (size_t)n0g * D_;
    const float* bi = isV ? biasV + (n0g - 1024) : biasK + n0g;

    const int t    = threadIdx.x;
    const int lane = t & 31;
    const int warp = t >> 5;
    const int qr = lane >> 2;
    const int qc = lane & 3;
    const int wm = warp >> 2;
    const int wn = warp & 3;

    const unsigned lrow = (lane & 7) + ((lane >> 3) & 1) * 8;
    const unsigned lcolb = (lane >> 4) * 16;
    const unsigned brow = (lane >> 4) * 8 + (lane & 7);
    const unsigned bcolb = ((lane >> 3) & 1) * 16;

    auto issue = [&](int st, int k0) {
        unsigned ab = smb + (unsigned)(st * 4608 * 4);
        unsigned bb = smb + (unsigned)((9216 + st * 4608) * 4);
        #pragma unroll
        for (int l = 0; l < 4; l++) {
            int idx = t + l * 256;
            int r = idx >> 3, cc = (idx & 7) << 2;
            cpa16(ab + (unsigned)((r * 36 + cc) * 4),
                  A + (size_t)(m0 + r) * D_ + k0 + cc);
        }
        #pragma unroll
        for (int l = 0; l < 4; l++) {
            int idx = t + l * 256;
            int r = idx >> 3, cc = (idx & 7) << 2;
            cpa16(bb + (unsigned)((r * 36 + cc) * 4),
                  Bt + (size_t)r * D_ + k0 + cc);
        }
        cpa_commit();
    };

    float c[4][4][4] = {};

    issue(0, 0);
    issue(1, 32);

    const int NT = D_ / 32;
    for (int kt = 0; kt < NT; kt++) {
        if (kt < NT - 1) cpa_wait<1>(); else cpa_wait<0>();
        __syncthreads();

        unsigned abase = smb + (unsigned)((kt & 1) * 4608 * 4);
        unsigned bbase = smb + (unsigned)((9216 + (kt & 1) * 4608) * 4);
        unsigned aaddr = abase + ((64 * wm + lrow) * 36) * 4 + lcolb;
        unsigned baddr = bbase + ((32 * wn + brow) * 36) * 4 + bcolb;

        #pragma unroll
        for (int k8 = 0; k8 < 4; k8++) {
            unsigned af[4][4];
            #pragma unroll
            for (int mi = 0; mi < 4; mi++)
                ldsm4(af[mi][0], af[mi][1], af[mi][2], af[mi][3],
                      aaddr + (unsigned)(mi * 16 * 36 * 4) + k8 * 32);
            #pragma unroll
            for (int jp = 0; jp < 2; jp++) {
                unsigned b0, b1, b2, b3;
                ldsm4(b0, b1, b2, b3, baddr + (unsigned)(jp * 16 * 36 * 4) + k8 * 32);
                #pragma unroll
                for (int mi = 0; mi < 4; mi++) {
                    mma_tf32(c[mi][2 * jp],     af[mi][0], af[mi][1], af[mi][2], af[mi][3], b0, b1);
                    mma_tf32(c[mi][2 * jp + 1], af[mi][0], af[mi][1], af[mi][2], af[mi][3], b2, b3);
                }
            }
        }
        __syncthreads();
        if (kt + 2 < NT) issue(kt & 1, (kt + 2) * 32);
    }

    #pragma unroll
    for (int mi = 0; mi < 4; mi++) {
        int r0 = m0 + 64 * wm + 16 * mi + qr;
        int bb = r0 >> 11;
        int sq = r0 & 2047;
        #pragma unroll
        for (int nj = 0; nj < 4; nj++) {
            int lc = 32 * wn + 8 * nj + 2 * qc;
            float2 bv2 = *(const float2*)(bi + lc);
            float v00 = c[mi][nj][0] + bv2.x, v01 = c[mi][nj][1] + bv2.y;
            float v10 = c[mi][nj][2] + bv2.x, v11 = c[mi][nj][3] + bv2.y;
            if (MODE == 0) {
                int gcol = n0g + lc;
                int h = gcol >> 6, e = gcol & 63;
                float* O = OutK + ((size_t)(bb * H_ + h) * SQ_ + sq) * HD_ + e;
                *(float2*)O = make_float2(rndtf(v00 * SCALE_Q), rndtf(v01 * SCALE_Q));
                *(float2*)(O + 8 * HD_) = make_float2(rndtf(v10 * SCALE_Q), rndtf(v11 * SCALE_Q));
            } else if (!isV) {
                int gcol = n0g + lc;
                int h = gcol >> 6, e = gcol & 63;
                float* O = OutK + ((size_t)(bb * H_ + h) * SQ_ + sq) * HD_ + e;
                *(float2*)O = make_float2(rndtf(v00), rndtf(v01));
                *(float2*)(O + 8 * HD_) = make_float2(rndtf(v10), rndtf(v11));
            } else {
                int le = (n0g - 1024) + lc;
                int h = le >> 6, hd = le & 63;
                float* O = OutV + ((size_t)(bb * H_ + h) * HD_ + hd) * SK_ + sq;
                O[0] = rndtf(v00);
                O[SK_] = rndtf(v01);
                O[8] = rndtf(v10);
                O[SK_ + 8] = rndtf(v11);
            }
        }
    }
}

// ---------------------------------------------------------------------------
// Output GEMM (1xTF32, LDSM fragments, 2-stage cp.async). Unchanged.
// ---------------------------------------------------------------------------
__global__ __launch_bounds__(256) void ogemm_kernel(
    const float* __restrict__ A, const float* __restrict__ Wt,
    const float* __restrict__ bias, float* __restrict__ Out)
{
    extern __shared__ float sm[];
    const unsigned smb = (unsigned)__cvta_generic_to_shared(sm);

    const int m0 = blockIdx.x * 128;
    const int n0 = blockIdx.y * 128;
    const int t    = threadIdx.x;
    const int lane = t & 31;
    const int warp = t >> 5;
    const int qr = lane >> 2;
    const int qc = lane & 3;
    const int wm = warp >> 2;
    const int wn = warp & 3;

    const unsigned lrow = (lane & 7) + ((lane >> 3) & 1) * 8;
    const unsigned lcolb = (lane >> 4) * 16;
    const unsigned brow = (lane >> 4) * 8 + (lane & 7);
    const unsigned bcolb = ((lane >> 3) & 1) * 16;

    auto issue = [&](int st, int k0) {
        unsigned ab = smb + (unsigned)(st * 4608 * 4);
        unsigned bb = smb + (unsigned)((9216 + st * 4608) * 4);
        #pragma unroll
        for (int l = 0; l < 4; l++) {
            int idx = t + l * 256;
            int r = idx >> 3, cc = (idx & 7) << 2;
            cpa16(ab + (unsigned)((r * 36 + cc) * 4),
                  A + (size_t)(m0 + r) * D_ + k0 + cc);
        }
        #pragma unroll
        for (int l = 0; l < 4; l++) {
            int idx = t + l * 256;
            int r = idx >> 3, cc = (idx & 7) << 2;
            cpa16(bb + (unsigned)((r * 36 + cc) * 4),
                  Wt + (size_t)(n0 + r) * D_ + k0 + cc);
        }
        cpa_commit();
    };

    float c[4][4][4] = {};

    issue(0, 0);
    issue(1, 32);

    const int NT = D_ / 32;
    for (int kt = 0; kt < NT; kt++) {
        if (kt < NT - 1) cpa_wait<1>(); else cpa_wait<0>();
        __syncthreads();

        unsigned abase = smb + (unsigned)((kt & 1) * 4608 * 4);
        unsigned bbase = smb + (unsigned)((9216 + (kt & 1) * 4608) * 4);
        unsigned aaddr = abase + ((64 * wm + lrow) * 36) * 4 + lcolb;
        unsigned baddr = bbase + ((32 * wn + brow) * 36) * 4 + bcolb;

        #pragma unroll
        for (int k8 = 0; k8 < 4; k8++) {
            unsigned af[4][4];
            #pragma unroll
            for (int mi = 0; mi < 4; mi++)
                ldsm4(af[mi][0], af[mi][1], af[mi][2], af[mi][3],
                      aaddr + (unsigned)(mi * 16 * 36 * 4) + k8 * 32);
            #pragma unroll
            for (int jp = 0; jp < 2; jp++) {
                unsigned b0, b1, b2, b3;
                ldsm4(b0, b1, b2, b3, baddr + (unsigned)(jp * 16 * 36 * 4) + k8 * 32);
                #pragma unroll
                for (int mi = 0; mi < 4; mi++) {
                    mma_tf32(c[mi][2 * jp],     af[mi][0], af[mi][1], af[mi][2], af[mi][3], b0, b1);
                    mma_tf32(c[mi][2 * jp + 1], af[mi][0], af[mi][1], af[mi][2], af[mi][3], b2, b3);
                }
            }
        }
        __syncthreads();
        if (kt + 2 < NT) issue(kt & 1, (kt + 2) * 32);
    }

    #pragma unroll
    for (int mi = 0; mi < 4; mi++) {
        int r0 = m0 + 64 * wm + 16 * mi + qr;
        #pragma unroll
        for (int nj = 0; nj < 4; nj++) {
            int col = n0 + 32 * wn + 8 * nj + 2 * qc;
            float2 bb = *(const float2*)(bias + col);
            *(float2*)(Out + (size_t)r0 * D_ + col) =
                make_float2(c[mi][nj][0] + bb.x, c[mi][nj][1] + bb.y);
            *(float2*)(Out + (size_t)(r0 + 8) * D_ + col) =
                make_float2(c[mi][nj][2] + bb.x, c[mi][nj][3] + bb.y);
        }
    }
}

// ---------------------------------------------------------------------------
// Flash attention: tf32 mma, exp2 softmax (no online max), register-resident
// Q fragments, 3-stage KV pipeline (stage 2 recycles the Q staging buffer).
// smem = 3 stages x (K[64][68] | V[64][68]) = 104448 B (unchanged).
// ---------------------------------------------------------------------------
__global__ __launch_bounds__(256) void attn_kernel(
    const float* __restrict__ Qg, const float* __restrict__ Kg,
    const float* __restrict__ Vg, float* __restrict__ Og)
{
    extern __shared__ float sm[];
    const unsigned smb = (unsigned)__cvta_generic_to_shared(sm);
    const unsigned STSZ = 2 * 64 * 68;     // floats per stage (= Q buffer size)
    const unsigned VOFF = 64 * 68;

    const int q0 = blockIdx.x * 128;
    const int h  = blockIdx.y;
    const int b  = blockIdx.z;
    const int t    = threadIdx.x;
    const int lane = t & 31;
    const int warp = t >> 5;
    const int qr = lane >> 2;
    const int qc = lane & 3;
    const int rowbase = 16 * warp;

    const size_t bh = (size_t)(b * H_ + h);
    const float* Q = Qg + bh * SQ_ * HD_;
    const float* K = Kg + bh * SK_ * HD_;
    const float* V = Vg + bh * HD_ * SK_;

    const unsigned a_off = ((unsigned)((rowbase + (lane & 7) + ((lane >> 3) & 1) * 8) * 68)
                            + (lane >> 4) * 4) * 4;
    const unsigned b_off = ((unsigned)((((lane >> 4) * 8) + (lane & 7)) * 68)
                            + ((lane >> 3) & 1) * 4) * 4;

    auto issueKV = [&](int st, int j0) {
        unsigned kb = smb + (unsigned)st * STSZ * 4;
        unsigned vb = kb + VOFF * 4;
        #pragma unroll
        for (int l = 0; l < 4; l++) {
            int idx = t + l * 256;
            int r = idx >> 4, cc = (idx & 15) << 2;
            cpa16(kb + (unsigned)((r * 68 + cc) * 4), K + (size_t)(j0 + r) * HD_ + cc);
        }
        #pragma unroll
        for (int l = 0; l < 4; l++) {
            int idx = t + l * 256;
            int e = idx >> 4, kk = (idx & 15) << 2;
            cpa16(vb + (unsigned)((e * 68 + kk) * 4), V + (size_t)e * SK_ + j0 + kk);
        }
        cpa_commit();
    };

    // Stage Q into S2, then KV0->S0, KV1->S1
    {
        unsigned qb = smb + 2u * STSZ * 4;
        #pragma unroll
        for (int l = 0; l < 8; l++) {
            int idx = t + l * 256;
            int r = idx >> 4, cc = (idx & 15) << 2;
            cpa16(qb + (unsigned)((r * 68 + cc) * 4), Q + (size_t)(q0 + r) * HD_ + cc);
        }
        cpa_commit();          // G0 = Q
    }
    issueKV(0, 0);             // G1
    issueKV(1, 64);            // G2

    cpa_wait<2>();             // Q complete
    __syncthreads();

    // Extract Q fragments once (warp rows are fixed for the whole kernel)
    unsigned qf[8][4];
    {
        unsigned qaddr = smb + 2u * STSZ * 4 + a_off;
        #pragma unroll
        for (int k8 = 0; k8 < 8; k8++)
            ldsm4(qf[k8][0], qf[k8][1], qf[k8][2], qf[k8][3], qaddr + k8 * 32);
    }
    __syncthreads();           // all warps done reading S2 before iter0 reuses it

    float o[8][4] = {};
    float lrow0 = 0.0f, lrow1 = 0.0f;

    const int src_lo = (lane & ~3) | (qc >> 1);
    const int src_hi = src_lo + 2;
    const bool odd = qc & 1;

    const int NT = SK_ / 64;   // 32
    int stj = 0;               // j % 3
    for (int j = 0; j < NT; j++) {
        // prefetch KV(j+2) into the stage freed after compute (j-1)
        if (j + 2 < NT) {
            int st2 = stj + 2; if (st2 >= 3) st2 -= 3;
            issueKV(st2, (j + 2) * 64);
        }
        if (j < NT - 2) cpa_wait<2>();
        else if (j == NT - 2) cpa_wait<1>();
        else cpa_wait<0>();
        __syncthreads();

        const unsigned kbase = smb + (unsigned)stj * STSZ * 4;
        const unsigned vbase = kbase + VOFF * 4;

        // S = Q K^T (log2 domain)
        float s[8][4] = {};
        #pragma unroll
        for (int k8 = 0; k8 < 8; k8++) {
            #pragma unroll
            for (int jp = 0; jp < 4; jp++) {
                unsigned b0, b1, b2, b3;
                ldsm4(b0, b1, b2, b3, kbase + b_off + (unsigned)(jp * 16 * 68 * 4) + k8 * 32);
                mma_tf32(s[2 * jp],     qf[k8][0], qf[k8][1], qf[k8][2], qf[k8][3], b0, b1);
                mma_tf32(s[2 * jp + 1], qf[k8][0], qf[k8][1], qf[k8][2], qf[k8][3], b2, b3);
            }
        }

        // P = exp2(S); per-thread partial row sums
        #pragma unroll
        for (int jj = 0; jj < 8; jj++) {
            s[jj][0] = exp2f(s[jj][0]);
            s[jj][1] = exp2f(s[jj][1]);
            s[jj][2] = exp2f(s[jj][2]);
            s[jj][3] = exp2f(s[jj][3]);
            lrow0 += s[jj][0] + s[jj][1];
            lrow1 += s[jj][2] + s[jj][3];
        }

        // O += P V (P A-fragments via quad shfl)
        #pragma unroll
        for (int k8 = 0; k8 < 8; k8++) {
            float e00 = __shfl_sync(0xffffffffu, s[k8][0], src_lo);
            float e01 = __shfl_sync(0xffffffffu, s[k8][1], src_lo);
            float e10 = __shfl_sync(0xffffffffu, s[k8][2], src_lo);
            float e11 = __shfl_sync(0xffffffffu, s[k8][3], src_lo);
            float f00 = __shfl_sync(0xffffffffu, s[k8][0], src_hi);
            float f01 = __shfl_sync(0xffffffffu, s[k8][1], src_hi);
            float f10 = __shfl_sync(0xffffffffu, s[k8][2], src_hi);
            float f11 = __shfl_sync(0xffffffffu, s[k8][3], src_hi);
            unsigned a0 = f2tf(odd ? e01 : e00);
            unsigned a1 = f2tf(odd ? e11 : e10);
            unsigned a2 = f2tf(odd ? f01 : f00);
            unsigned a3 = f2tf(odd ? f11 : f10);
            #pragma unroll
            for (int jp = 0; jp < 4; jp++) {
                unsigned b0, b1, b2, b3;
                ldsm4(b0, b1, b2, b3, vbase + b_off + (unsigned)(jp * 16 * 68 * 4) + k8 * 32);
                mma_tf32(o[2 * jp],     a0, a1, a2, a3, b0, b1);
                mma_tf32(o[2 * jp + 1], a0, a1, a2, a3, b2, b3);
            }
        }

        __syncthreads();   // stage stj free for the prefetch issued at top of j+1
        if (++stj == 3) stj = 0;
    }

    // Epilogue: quad-reduce row sums once, normalize, round, store
    lrow0 += __shfl_xor_sync(0xffffffffu, lrow0, 1);
    lrow0 += __shfl_xor_sync(0xffffffffu, lrow0, 2);
    lrow1 += __shfl_xor_sync(0xffffffffu, lrow1, 1);
    lrow1 += __shfl_xor_sync(0xffffffffu, lrow1, 2);
    float inv0 = 1.0f / lrow0, inv1 = 1.0f / lrow1;

    int r0 = q0 + rowbase + qr;
    float* O0 = Og + ((size_t)b * SQ_ + r0) * D_ + h * HD_;
    float* O1 = O0 + (size_t)8 * D_;
    #pragma unroll
    for (int jj = 0; jj < 8; jj++) {
        int col = 8 * jj + 2 * qc;
        *(float2*)(O0 + col) = make_float2(rndtf(o[jj][0] * inv0), rndtf(o[jj][1] * inv0));
        *(float2*)(O1 + col) = make_float2(rndtf(o[jj][2] * inv1), rndtf(o[jj][3] * inv1));
    }
}

// ---------------------------------------------------------------------------
// Launch
// ---------------------------------------------------------------------------
extern "C" void kernel_launch(void* const* d_in, const int* in_sizes, int n_in,
                              void* d_out, int out_size)
{
    const float* x   = (const float*)d_in[0];
    const float* enc = (const float*)d_in[1];
    const float* Wq  = (const float*)d_in[2];
    const float* bq  = (const float*)d_in[3];
    const float* Wk  = (const float*)d_in[4];
    const float* bk  = (const float*)d_in[5];
    const float* Wv  = (const float*)d_in[6];
    const float* bv  = (const float*)d_in[7];
    const float* Wo  = (const float*)d_in[8];
    const float* bo  = (const float*)d_in[9];
    float* out = (float*)d_out;

    float *q, *k, *v, *attn, *xr, *encr, *wqt, *wkt, *wvt, *wot;
    cudaGetSymbolAddress((void**)&q, g_q);
    cudaGetSymbolAddress((void**)&k, g_k);
    cudaGetSymbolAddress((void**)&v, g_v);
    cudaGetSymbolAddress((void**)&attn, g_attn);
    cudaGetSymbolAddress((void**)&xr, g_xr);
    cudaGetSymbolAddress((void**)&encr, g_encr);
    cudaGetSymbolAddress((void**)&wqt, g_wqt);
    cudaGetSymbolAddress((void**)&wkt, g_wkt);
    cudaGetSymbolAddress((void**)&wvt, g_wvt);
    cudaGetSymbolAddress((void**)&wot, g_wot);

    // prep (3 launches)
    const int nxd4 = B_ * SQ_ * D_ / 4;
    round2_kernel<<<dim3(nxd4 / 256, 2), 256>>>(x, enc, xr, encr, nxd4);
    tround3_kernel<<<dim3(HD_ / 32, D_ / 32, 3 * H_), 256>>>(
        Wq, Wk, Wv, wqt, wkt, wvt, D_, HD_);
    tround_kernel<<<dim3(D_ / 32, D_ / 32), 256>>>(Wo, wot, D_, D_);

    const int gsm = (2 * 4608 + 2 * 4608) * (int)sizeof(float);  // 73728
    cudaFuncSetAttribute(gemm_big<0>, cudaFuncAttributeMaxDynamicSharedMemorySize, gsm);
    cudaFuncSetAttribute(gemm_big<1>, cudaFuncAttributeMaxDynamicSharedMemorySize, gsm);
    cudaFuncSetAttribute(ogemm_kernel, cudaFuncAttributeMaxDynamicSharedMemorySize, gsm);

    gemm_big<0><<<dim3((B_ * SQ_) / 128, (H_ * HD_) / 128), 256, gsm>>>(
        xr, wqt, nullptr, bq, nullptr, q, nullptr);
    gemm_big<1><<<dim3((B_ * SK_) / 128, (2 * H_ * HD_) / 128), 256, gsm>>>(
        encr, wkt, wvt, bk, bv, k, v);

    const int attn_smem = 3 * 2 * 64 * 68 * (int)sizeof(float); // 104448
    cudaFuncSetAttribute(attn_kernel, cudaFuncAttributeMaxDynamicSharedMemorySize, attn_smem);
    dim3 agrid(SQ_ / 128, H_, B_);
    attn_kernel<<<agrid, 256, attn_smem>>>(q, k, v, attn);

    ogemm_kernel<<<dim3((B_ * SQ_) / 128, D_ / 128), 256, gsm>>>(attn, wot, bo, out);
}

// round 15
// speedup vs baseline: 1.1037x; 1.1037x over previous
#include <cuda_runtime.h>
#include <cstdint>
#include <math.h>

#define B_  2
#define SQ_ 2048
#define SK_ 2048
#define D_  1024
#define H_  16
#define HD_ 64
#define SCALE_Q 0.180336880f   // 0.125 * log2(e); softmax via exp2

// ---------------------------------------------------------------------------
// Scratch (device globals — no allocation allowed)
// ---------------------------------------------------------------------------
__device__ float g_q[(size_t)B_ * H_ * SQ_ * HD_];     // rounded, pre-scaled by SCALE_Q
__device__ float g_k[(size_t)B_ * H_ * SK_ * HD_];     // rounded
__device__ float g_v[(size_t)B_ * H_ * HD_ * SK_];     // rounded, TRANSPOSED [hd][sk]
__device__ float g_attn[(size_t)B_ * SQ_ * D_];        // rounded
__device__ float g_xr[(size_t)B_ * SQ_ * D_];          // rounded x
__device__ float g_encr[(size_t)B_ * SK_ * D_];        // rounded enc
__device__ float g_wqt[(size_t)H_ * HD_ * D_];         // rounded, transposed: [h*HD+e][D]
__device__ float g_wkt[(size_t)H_ * HD_ * D_];
__device__ float g_wvt[(size_t)H_ * HD_ * D_];
__device__ float g_wot[(size_t)D_ * D_];               // rounded, transposed [n][k]

// ---------------------------------------------------------------------------
// helpers
// ---------------------------------------------------------------------------
__device__ __forceinline__ unsigned f2tf(float x) {
    unsigned u;
    asm("cvt.rna.tf32.f32 %0, %1;" : "=r"(u) : "f"(x));
    return u;
}
__device__ __forceinline__ float rndtf(float x) { return __uint_as_float(f2tf(x)); }

__device__ __forceinline__ void mma_tf32(float c[4],
    unsigned a0, unsigned a1, unsigned a2, unsigned a3,
    unsigned b0, unsigned b1)
{
    asm volatile(
        "mma.sync.aligned.m16n8k8.row.col.f32.tf32.tf32.f32 "
        "{%0,%1,%2,%3}, {%4,%5,%6,%7}, {%8,%9}, {%0,%1,%2,%3};\n"
        : "+f"(c[0]), "+f"(c[1]), "+f"(c[2]), "+f"(c[3])
        : "r"(a0), "r"(a1), "r"(a2), "r"(a3), "r"(b0), "r"(b1));
}

__device__ __forceinline__ void ldsm4(unsigned& r0, unsigned& r1,
                                      unsigned& r2, unsigned& r3, unsigned addr)
{
    asm volatile("ldmatrix.sync.aligned.m8n8.x4.shared.b16 {%0,%1,%2,%3}, [%4];"
        : "=r"(r0), "=r"(r1), "=r"(r2), "=r"(r3) : "r"(addr));
}

__device__ __forceinline__ void cpa16(unsigned dst, const void* src) {
    asm volatile("cp.async.cg.shared.global [%0], [%1], 16;" :: "r"(dst), "l"(src));
}
__device__ __forceinline__ void cpa_commit() {
    asm volatile("cp.async.commit_group;");
}
template <int N>
__device__ __forceinline__ void cpa_wait() {
    asm volatile("cp.async.wait_group %0;" :: "n"(N));
}

// ---------------------------------------------------------------------------
// Prep: round x and enc in one launch (blockIdx.y selects)
// ---------------------------------------------------------------------------
__global__ __launch_bounds__(256) void round2_kernel(
    const float* __restrict__ s0, const float* __restrict__ s1,
    float* __restrict__ d0, float* __restrict__ d1, int n4)
{
    int i = blockIdx.x * 256 + threadIdx.x;
    const float* s = blockIdx.y ? s1 : s0;
    float* d = blockIdx.y ? d1 : d0;
    if (i < n4) {
        float4 v = ((const float4*)s)[i];
        v.x = rndtf(v.x); v.y = rndtf(v.y);
        v.z = rndtf(v.z); v.w = rndtf(v.w);
        ((float4*)d)[i] = v;
    }
}

// ---------------------------------------------------------------------------
// Prep: transpose + round for the three QKV weights in one launch.
// ---------------------------------------------------------------------------
__global__ __launch_bounds__(256) void tround3_kernel(
    const float* __restrict__ s0, const float* __restrict__ s1,
    const float* __restrict__ s2,
    float* __restrict__ d0, float* __restrict__ d1, float* __restrict__ d2,
    int R, int C)
{
    __shared__ float tile[32][33];
    int zz = blockIdx.z;
    int which = zz >> 4;
    int z = zz & 15;
    const float* src = (which == 0) ? s0 : (which == 1) ? s1 : s2;
    float* dst = (which == 0) ? d0 : (which == 1) ? d1 : d2;
    src += (size_t)z * R * C;
    dst += (size_t)z * R * C;
    int c0 = blockIdx.x * 32, r0 = blockIdx.y * 32;
    int tx = threadIdx.x & 31, ty = threadIdx.x >> 5;

    #pragma unroll
    for (int i = ty; i < 32; i += 8)
        tile[i][tx] = src[(size_t)(r0 + i) * C + c0 + tx];
    __syncthreads();
    #pragma unroll
    for (int i = ty; i < 32; i += 8)
        dst[(size_t)(c0 + i) * R + r0 + tx] = rndtf(tile[tx][i]);
}

// ---------------------------------------------------------------------------
// Prep: transpose + round (single matrix, for Wo)
// ---------------------------------------------------------------------------
__global__ __launch_bounds__(256) void tround_kernel(
    const float* __restrict__ src, float* __restrict__ dst, int R, int C)
{
    __shared__ float tile[32][33];
    int c0 = blockIdx.x * 32, r0 = blockIdx.y * 32;
    int tx = threadIdx.x & 31, ty = threadIdx.x >> 5;

    #pragma unroll
    for (int i = ty; i < 32; i += 8)
        tile[i][tx] = src[(size_t)(r0 + i) * C + c0 + tx];
    __syncthreads();
    #pragma unroll
    for (int i = ty; i < 32; i += 8)
        dst[(size_t)(c0 + i) * R + r0 + tx] = rndtf(tile[tx][i]);
}

// ---------------------------------------------------------------------------
// Fused projection GEMM: 1xTF32, SW128-swizzled tiles, 3-stage cp.async,
// ONE __syncthreads per K-tile. Tile 128x128x32, 8 warps as 2(M)x4(N).
// Stage (32768 B): A[128 rows][128 B] then B[128 rows][128 B].
// MODE 0: Q gemm (N=1024); MODE 1: KV gemm (N=2048).
// ---------------------------------------------------------------------------
template <int MODE>
__global__ __launch_bounds__(256) void gemm_big(
    const float* __restrict__ A, const float* __restrict__ BtK,
    const float* __restrict__ BtV, const float* __restrict__ biasK,
    const float* __restrict__ biasV, float* __restrict__ OutK,
    float* __restrict__ OutV)
{
    extern __shared__ float sm[];
    const unsigned smb = (unsigned)__cvta_generic_to_shared(sm);

    const int m0  = blockIdx.x * 128;
    const int n0g = blockIdx.y * 128;
    const bool isV = (MODE == 1) && (n0g >= 1024);
    const float* Bt = isV ? BtV + (size_t)(n0g - 1024) * D_
                          : BtK + (size_t)n0g * D_;
    const float* bi = isV ? biasV + (n0g - 1024) : biasK + n0g;

    const int t    = threadIdx.x;
    const int lane = t & 31;
    const int warp = t >> 5;
    const int qr = lane >> 2;
    const int qc = lane & 3;
    const int wm = warp >> 2;   // M offset 64*wm
    const int wn = warp & 3;    // N offset 32*wn

    // fragment lane geometry
    const unsigned lrow = (lane & 7) + ((lane >> 3) & 1) * 8;   // A 16-row group
    const unsigned acol = (lane >> 4) * 16;                      // A col bytes
    const unsigned browl = (lane >> 4) * 8 + (lane & 7);         // B 16-row group
    const unsigned bcol = ((lane >> 3) & 1) * 16;                // B col bytes

    unsigned arow[4], aswz[4];
    #pragma unroll
    for (int mi = 0; mi < 4; mi++) {
        unsigned row = 64 * wm + 16 * mi + lrow;
        arow[mi] = row * 128;
        aswz[mi] = (arow[mi] >> 3) & 0x70;
    }
    unsigned brow[2], bswz[2];
    #pragma unroll
    for (int jp = 0; jp < 2; jp++) {
        unsigned row = 32 * wn + 16 * jp + browl;
        brow[jp] = row * 128;
        bswz[jp] = (brow[jp] >> 3) & 0x70;
    }

    auto issue = [&](int st, int k0) {
        unsigned ab = smb + (unsigned)st * 32768u;
        unsigned bb = ab + 16384u;
        #pragma unroll
        for (int l = 0; l < 4; l++) {            // A: 128 rows x 8 chunks
            int idx = t + l * 256;
            int r = idx >> 3, ch = idx & 7;
            unsigned off = (unsigned)(r * 128 + ch * 16);
            off ^= (off >> 3) & 0x70;
            cpa16(ab + off, A + (size_t)(m0 + r) * D_ + k0 + ch * 4);
        }
        #pragma unroll
        for (int l = 0; l < 4; l++) {            // B: 128 n-rows x 8 chunks
            int idx = t + l * 256;
            int r = idx >> 3, ch = idx & 7;
            unsigned off = (unsigned)(r * 128 + ch * 16);
            off ^= (off >> 3) & 0x70;
            cpa16(bb + off, Bt + (size_t)r * D_ + k0 + ch * 4);
        }
        cpa_commit();
    };

    float c[4][4][4] = {};

    issue(0, 0);
    issue(1, 32);

    const int NT = D_ / 32;   // 32
    int st = 0;
    for (int kt = 0; kt < NT; kt++) {
        if (kt < NT - 1) cpa_wait<1>(); else cpa_wait<0>();
        __syncthreads();   // stage st data visible to all; readers of stage (kt-1)%3 done
        if (kt + 2 < NT) {
            int s2 = st + 2; if (s2 >= 3) s2 -= 3;
            issue(s2, (kt + 2) * 32);
        }

        unsigned abase = smb + (unsigned)st * 32768u;
        unsigned bbase = abase + 16384u;

        #pragma unroll
        for (int k8 = 0; k8 < 4; k8++) {
            unsigned af[4][4];
            #pragma unroll
            for (int mi = 0; mi < 4; mi++)
                ldsm4(af[mi][0], af[mi][1], af[mi][2], af[mi][3],
                      abase + arow[mi] + ((acol + k8 * 32) ^ aswz[mi]));
            #pragma unroll
            for (int jp = 0; jp < 2; jp++) {
                unsigned b0, b1, b2, b3;
                ldsm4(b0, b1, b2, b3,
                      bbase + brow[jp] + ((bcol + k8 * 32) ^ bswz[jp]));
                #pragma unroll
                for (int mi = 0; mi < 4; mi++) {
                    mma_tf32(c[mi][2 * jp],     af[mi][0], af[mi][1], af[mi][2], af[mi][3], b0, b1);
                    mma_tf32(c[mi][2 * jp + 1], af[mi][0], af[mi][1], af[mi][2], af[mi][3], b2, b3);
                }
            }
        }
        if (++st == 3) st = 0;
    }

    #pragma unroll
    for (int mi = 0; mi < 4; mi++) {
        int r0 = m0 + 64 * wm + 16 * mi + qr;
        int bb = r0 >> 11;
        int sq = r0 & 2047;
        #pragma unroll
        for (int nj = 0; nj < 4; nj++) {
            int lc = 32 * wn + 8 * nj + 2 * qc;
            float2 bv2 = *(const float2*)(bi + lc);
            float v00 = c[mi][nj][0] + bv2.x, v01 = c[mi][nj][1] + bv2.y;
            float v10 = c[mi][nj][2] + bv2.x, v11 = c[mi][nj][3] + bv2.y;
            if (MODE == 0) {
                int gcol = n0g + lc;
                int h = gcol >> 6, e = gcol & 63;
                float* O = OutK + ((size_t)(bb * H_ + h) * SQ_ + sq) * HD_ + e;
                *(float2*)O = make_float2(rndtf(v00 * SCALE_Q), rndtf(v01 * SCALE_Q));
                *(float2*)(O + 8 * HD_) = make_float2(rndtf(v10 * SCALE_Q), rndtf(v11 * SCALE_Q));
            } else if (!isV) {
                int gcol = n0g + lc;
                int h = gcol >> 6, e = gcol & 63;
                float* O = OutK + ((size_t)(bb * H_ + h) * SQ_ + sq) * HD_ + e;
                *(float2*)O = make_float2(rndtf(v00), rndtf(v01));
                *(float2*)(O + 8 * HD_) = make_float2(rndtf(v10), rndtf(v11));
            } else {
                int le = (n0g - 1024) + lc;
                int h = le >> 6, hd = le & 63;
                float* O = OutV + ((size_t)(bb * H_ + h) * HD_ + hd) * SK_ + sq;
                O[0] = rndtf(v00);
                O[SK_] = rndtf(v01);
                O[8] = rndtf(v10);
                O[SK_ + 8] = rndtf(v11);
            }
        }
    }
}

// ---------------------------------------------------------------------------
// Output GEMM: same 3-stage swizzled single-sync pipeline.
// ---------------------------------------------------------------------------
__global__ __launch_bounds__(256) void ogemm_kernel(
    const float* __restrict__ A, const float* __restrict__ Wt,
    const float* __restrict__ bias, float* __restrict__ Out)
{
    extern __shared__ float sm[];
    const unsigned smb = (unsigned)__cvta_generic_to_shared(sm);

    const int m0 = blockIdx.x * 128;
    const int n0 = blockIdx.y * 128;
    const int t    = threadIdx.x;
    const int lane = t & 31;
    const int warp = t >> 5;
    const int qr = lane >> 2;
    const int qc = lane & 3;
    const int wm = warp >> 2;
    const int wn = warp & 3;

    const unsigned lrow = (lane & 7) + ((lane >> 3) & 1) * 8;
    const unsigned acol = (lane >> 4) * 16;
    const unsigned browl = (lane >> 4) * 8 + (lane & 7);
    const unsigned bcol = ((lane >> 3) & 1) * 16;

    unsigned arow[4], aswz[4];
    #pragma unroll
    for (int mi = 0; mi < 4; mi++) {
        unsigned row = 64 * wm + 16 * mi + lrow;
        arow[mi] = row * 128;
        aswz[mi] = (arow[mi] >> 3) & 0x70;
    }
    unsigned brow[2], bswz[2];
    #pragma unroll
    for (int jp = 0; jp < 2; jp++) {
        unsigned row = 32 * wn + 16 * jp + browl;
        brow[jp] = row * 128;
        bswz[jp] = (brow[jp] >> 3) & 0x70;
    }

    auto issue = [&](int st, int k0) {
        unsigned ab = smb + (unsigned)st * 32768u;
        unsigned bb = ab + 16384u;
        #pragma unroll
        for (int l = 0; l < 4; l++) {
            int idx = t + l * 256;
            int r = idx >> 3, ch = idx & 7;
            unsigned off = (unsigned)(r * 128 + ch * 16);
            off ^= (off >> 3) & 0x70;
            cpa16(ab + off, A + (size_t)(m0 + r) * D_ + k0 + ch * 4);
        }
        #pragma unroll
        for (int l = 0; l < 4; l++) {
            int idx = t + l * 256;
            int r = idx >> 3, ch = idx & 7;
            unsigned off = (unsigned)(r * 128 + ch * 16);
            off ^= (off >> 3) & 0x70;
            cpa16(bb + off, Wt + (size_t)(n0 + r) * D_ + k0 + ch * 4);
        }
        cpa_commit();
    };

    float c[4][4][4] = {};

    issue(0, 0);
    issue(1, 32);

    const int NT = D_ / 32;
    int st = 0;
    for (int kt = 0; kt < NT; kt++) {
        if (kt < NT - 1) cpa_wait<1>(); else cpa_wait<0>();
        __syncthreads();
        if (kt + 2 < NT) {
            int s2 = st + 2; if (s2 >= 3) s2 -= 3;
            issue(s2, (kt + 2) * 32);
        }

        unsigned abase = smb + (unsigned)st * 32768u;
        unsigned bbase = abase + 16384u;

        #pragma unroll
        for (int k8 = 0; k8 < 4; k8++) {
            unsigned af[4][4];
            #pragma unroll
            for (int mi = 0; mi < 4; mi++)
                ldsm4(af[mi][0], af[mi][1], af[mi][2], af[mi][3],
                      abase + arow[mi] + ((acol + k8 * 32) ^ aswz[mi]));
            #pragma unroll
            for (int jp = 0; jp < 2; jp++) {
                unsigned b0, b1, b2, b3;
                ldsm4(b0, b1, b2, b3,
                      bbase + brow[jp] + ((bcol + k8 * 32) ^ bswz[jp]));
                #pragma unroll
                for (int mi = 0; mi < 4; mi++) {
                    mma_tf32(c[mi][2 * jp],     af[mi][0], af[mi][1], af[mi][2], af[mi][3], b0, b1);
                    mma_tf32(c[mi][2 * jp + 1], af[mi][0], af[mi][1], af[mi][2], af[mi][3], b2, b3);
                }
            }
        }
        if (++st == 3) st = 0;
    }

    #pragma unroll
    for (int mi = 0; mi < 4; mi++) {
        int r0 = m0 + 64 * wm + 16 * mi + qr;
        #pragma unroll
        for (int nj = 0; nj < 4; nj++) {
            int col = n0 + 32 * wn + 8 * nj + 2 * qc;
            float2 bb = *(const float2*)(bias + col);
            *(float2*)(Out + (size_t)r0 * D_ + col) =
                make_float2(c[mi][nj][0] + bb.x, c[mi][nj][1] + bb.y);
            *(float2*)(Out + (size_t)(r0 + 8) * D_ + col) =
                make_float2(c[mi][nj][2] + bb.x, c[mi][nj][3] + bb.y);
        }
    }
}

// ---------------------------------------------------------------------------
// Flash attention: tf32 mma, exp2 softmax (no online max), LDSM + register P,
// 2-stage cp.async K/V — the validated R12 version, unchanged.
// ---------------------------------------------------------------------------
__global__ __launch_bounds__(256) void attn_kernel(
    const float* __restrict__ Qg, const float* __restrict__ Kg,
    const float* __restrict__ Vg, float* __restrict__ Og)
{
    extern __shared__ float sm[];
    const unsigned smb = (unsigned)__cvta_generic_to_shared(sm);
    const unsigned QB = 0;
    const unsigned ST0 = 128 * 68;
    const unsigned STSZ = 2 * 64 * 68;
    const unsigned VOFF = 64 * 68;

    const int q0 = blockIdx.x * 128;
    const int h  = blockIdx.y;
    const int b  = blockIdx.z;
    const int t    = threadIdx.x;
    const int lane = t & 31;
    const int warp = t >> 5;
    const int qr = lane >> 2;
    const int qc = lane & 3;
    const int rowbase = 16 * warp;

    const size_t bh = (size_t)(b * H_ + h);
    const float* Q = Qg + bh * SQ_ * HD_;
    const float* K = Kg + bh * SK_ * HD_;
    const float* V = Vg + bh * HD_ * SK_;

    const unsigned a_off = ((unsigned)((rowbase + (lane & 7) + ((lane >> 3) & 1) * 8) * 68)
                            + (lane >> 4) * 4) * 4;
    const unsigned b_off = ((unsigned)((((lane >> 4) * 8) + (lane & 7)) * 68)
                            + ((lane >> 3) & 1) * 4) * 4;

    auto issueKV = [&](int st, int j0) {
        unsigned kb = smb + (ST0 + st * STSZ) * 4;
        unsigned vb = kb + VOFF * 4;
        #pragma unroll
        for (int l = 0; l < 4; l++) {
            int idx = t + l * 256;
            int r = idx >> 4, cc = (idx & 15) << 2;
            cpa16(kb + (unsigned)((r * 68 + cc) * 4), K + (size_t)(j0 + r) * HD_ + cc);
        }
        #pragma unroll
        for (int l = 0; l < 4; l++) {
            int idx = t + l * 256;
            int e = idx >> 4, kk = (idx & 15) << 2;
            cpa16(vb + (unsigned)((e * 68 + kk) * 4), V + (size_t)e * SK_ + j0 + kk);
        }
        cpa_commit();
    };

    #pragma unroll
    for (int l = 0; l < 8; l++) {
        int idx = t + l * 256;
        int r = idx >> 4, cc = (idx & 15) << 2;
        cpa16(smb + (unsigned)((QB + r * 68 + cc) * 4), Q + (size_t)(q0 + r) * HD_ + cc);
    }
    issueKV(0, 0);
    issueKV(1, 64);

    float o[8][4] = {};
    float lrow0 = 0.0f, lrow1 = 0.0f;

    const int src_lo = (lane & ~3) | (qc >> 1);
    const int src_hi = src_lo + 2;
    const bool odd = qc & 1;
    const unsigned a_addr = smb + a_off;

    const int NT = SK_ / 64;
    for (int j = 0; j < NT; j++) {
        if (j < NT - 1) cpa_wait<1>(); else cpa_wait<0>();
        __syncthreads();

        const unsigned kbase = smb + (ST0 + (j & 1) * STSZ) * 4;
        const unsigned vbase = kbase + VOFF * 4;

        // S = Q K^T (log2 domain)
        float s[8][4] = {};
        #pragma unroll
        for (int k8 = 0; k8 < 8; k8++) {
            unsigned a0, a1, a2, a3;
            ldsm4(a0, a1, a2, a3, a_addr + k8 * 32);
            #pragma unroll
            for (int jp = 0; jp < 4; jp++) {
                unsigned b0, b1, b2, b3;
                ldsm4(b0, b1, b2, b3, kbase + b_off + (unsigned)(jp * 16 * 68 * 4) + k8 * 32);
                mma_tf32(s[2 * jp],     a0, a1, a2, a3, b0, b1);
                mma_tf32(s[2 * jp + 1], a0, a1, a2, a3, b2, b3);
            }
        }

        // P = exp2(S); per-thread partial row sums
        #pragma unroll
        for (int jj = 0; jj < 8; jj++) {
            s[jj][0] = exp2f(s[jj][0]);
            s[jj][1] = exp2f(s[jj][1]);
            s[jj][2] = exp2f(s[jj][2]);
            s[jj][3] = exp2f(s[jj][3]);
            lrow0 += s[jj][0] + s[jj][1];
            lrow1 += s[jj][2] + s[jj][3];
        }

        // O += P V (P A-fragments via quad shfl)
        #pragma unroll
        for (int k8 = 0; k8 < 8; k8++) {
            float e00 = __shfl_sync(0xffffffffu, s[k8][0], src_lo);
            float e01 = __shfl_sync(0xffffffffu, s[k8][1], src_lo);
            float e10 = __shfl_sync(0xffffffffu, s[k8][2], src_lo);
            float e11 = __shfl_sync(0xffffffffu, s[k8][3], src_lo);
            float f00 = __shfl_sync(0xffffffffu, s[k8][0], src_hi);
            float f01 = __shfl_sync(0xffffffffu, s[k8][1], src_hi);
            float f10 = __shfl_sync(0xffffffffu, s[k8][2], src_hi);
            float f11 = __shfl_sync(0xffffffffu, s[k8][3], src_hi);
            unsigned a0 = f2tf(odd ? e01 : e00);
            unsigned a1 = f2tf(odd ? e11 : e10);
            unsigned a2 = f2tf(odd ? f01 : f00);
            unsigned a3 = f2tf(odd ? f11 : f10);
            #pragma unroll
            for (int jp = 0; jp < 4; jp++) {
                unsigned b0, b1, b2, b3;
                ldsm4(b0, b1, b2, b3, vbase + b_off + (unsigned)(jp * 16 * 68 * 4) + k8 * 32);
                mma_tf32(o[2 * jp],     a0, a1, a2, a3, b0, b1);
                mma_tf32(o[2 * jp + 1], a0, a1, a2, a3, b2, b3);
            }
        }

        __syncthreads();
        if (j + 2 < NT) issueKV(j & 1, (j + 2) * 64);
    }

    // Epilogue: quad-reduce row sums once, normalize, round, store
    lrow0 += __shfl_xor_sync(0xffffffffu, lrow0, 1);
    lrow0 += __shfl_xor_sync(0xffffffffu, lrow0, 2);
    lrow1 += __shfl_xor_sync(0xffffffffu, lrow1, 1);
    lrow1 += __shfl_xor_sync(0xffffffffu, lrow1, 2);
    float inv0 = 1.0f / lrow0, inv1 = 1.0f / lrow1;

    int r0 = q0 + rowbase + qr;
    float* O0 = Og + ((size_t)b * SQ_ + r0) * D_ + h * HD_;
    float* O1 = O0 + (size_t)8 * D_;
    #pragma unroll
    for (int jj = 0; jj < 8; jj++) {
        int col = 8 * jj + 2 * qc;
        *(float2*)(O0 + col) = make_float2(rndtf(o[jj][0] * inv0), rndtf(o[jj][1] * inv0));
        *(float2*)(O1 + col) = make_float2(rndtf(o[jj][2] * inv1), rndtf(o[jj][3] * inv1));
    }
}

// ---------------------------------------------------------------------------
// Launch
// ---------------------------------------------------------------------------
extern "C" void kernel_launch(void* const* d_in, const int* in_sizes, int n_in,
                              void* d_out, int out_size)
{
    const float* x   = (const float*)d_in[0];
    const float* enc = (const float*)d_in[1];
    const float* Wq  = (const float*)d_in[2];
    const float* bq  = (const float*)d_in[3];
    const float* Wk  = (const float*)d_in[4];
    const float* bk  = (const float*)d_in[5];
    const float* Wv  = (const float*)d_in[6];
    const float* bv  = (const float*)d_in[7];
    const float* Wo  = (const float*)d_in[8];
    const float* bo  = (const float*)d_in[9];
    float* out = (float*)d_out;

    float *q, *k, *v, *attn, *xr, *encr, *wqt, *wkt, *wvt, *wot;
    cudaGetSymbolAddress((void**)&q, g_q);
    cudaGetSymbolAddress((void**)&k, g_k);
    cudaGetSymbolAddress((void**)&v, g_v);
    cudaGetSymbolAddress((void**)&attn, g_attn);
    cudaGetSymbolAddress((void**)&xr, g_xr);
    cudaGetSymbolAddress((void**)&encr, g_encr);
    cudaGetSymbolAddress((void**)&wqt, g_wqt);
    cudaGetSymbolAddress((void**)&wkt, g_wkt);
    cudaGetSymbolAddress((void**)&wvt, g_wvt);
    cudaGetSymbolAddress((void**)&wot, g_wot);

    // prep (3 launches)
    const int nxd4 = B_ * SQ_ * D_ / 4;
    round2_kernel<<<dim3(nxd4 / 256, 2), 256>>>(x, enc, xr, encr, nxd4);
    tround3_kernel<<<dim3(HD_ / 32, D_ / 32, 3 * H_), 256>>>(
        Wq, Wk, Wv, wqt, wkt, wvt, D_, HD_);
    tround_kernel<<<dim3(D_ / 32, D_ / 32), 256>>>(Wo, wot, D_, D_);

    const int gsm = 3 * 32768;   // 98304 B: 3 stages x (A 16K | B 16K)
    cudaFuncSetAttribute(gemm_big<0>, cudaFuncAttributeMaxDynamicSharedMemorySize, gsm);
    cudaFuncSetAttribute(gemm_big<1>, cudaFuncAttributeMaxDynamicSharedMemorySize, gsm);
    cudaFuncSetAttribute(ogemm_kernel, cudaFuncAttributeMaxDynamicSharedMemorySize, gsm);

    gemm_big<0><<<dim3((B_ * SQ_) / 128, (H_ * HD_) / 128), 256, gsm>>>(
        xr, wqt, nullptr, bq, nullptr, q, nullptr);
    gemm_big<1><<<dim3((B_ * SK_) / 128, (2 * H_ * HD_) / 128), 256, gsm>>>(
        encr, wkt, wvt, bk, bv, k, v);

    const int attn_smem = (128 * 68 + 2 * 2 * 64 * 68) * (int)sizeof(float); // 104448
    cudaFuncSetAttribute(attn_kernel, cudaFuncAttributeMaxDynamicSharedMemorySize, attn_smem);
    dim3 agrid(SQ_ / 128, H_, B_);
    attn_kernel<<<agrid, 256, attn_smem>>>(q, k, v, attn);

    ogemm_kernel<<<dim3((B_ * SQ_) / 128, D_ / 128), 256, gsm>>>(attn, wot, bo, out);
}